// round 1
// baseline (speedup 1.0000x reference)
#include <cuda_runtime.h>
#include <math.h>

// Problem constants
#define Bb 8
#define Ss 512
#define Ll 512
#define Ee 768
#define Hh 12
#define HDd 64

// ---------------------------------------------------------------------------
// Scratch (device globals — no allocation allowed)
// ---------------------------------------------------------------------------
__device__ float g_wp0[Ee * Ee];                 // packed w_kx1 [E, H*HD]
__device__ float g_wp1[Ee * Ee];                 // packed w_qx1
__device__ float g_wp2[Ee * Ee];                 // packed w_kx2
__device__ float g_wp3[Ee * Ee];                 // packed w_qx2
__device__ float g_kx[Bb * Ss * Ee];             // keys  (concat-head layout)
__device__ float g_qx[Bb * Ss * Ee];             // queries
__device__ float g_scores[Bb * Hh * Ss * Ll];    // attention scores/probs
__device__ float g_att[Bb * Ss * Ee];            // attention output (concat)
__device__ float g_tmp[Bb * Ss * Ee];            // proj / ffn2 output
__device__ float g_Y[Bb * Ss * Ee];
__device__ float g_Z[Bb * Ss * Ee];
__device__ float g_hid[Bb * Ss * Ee];            // ffn hidden

// ---------------------------------------------------------------------------
// Weight pack: w[h, e, d] -> wp[e, h*HD + d]
// ---------------------------------------------------------------------------
__global__ void pack_w_kernel(const float* __restrict__ w, float* __restrict__ wp) {
    int idx = blockIdx.x * blockDim.x + threadIdx.x;
    if (idx >= Ee * Ee) return;
    int e = idx / Ee;
    int c = idx % Ee;
    int h = c / HDd;
    int d = c % HDd;
    wp[idx] = w[(h * Ee + e) * HDd + d];
}

// ---------------------------------------------------------------------------
// Tiled SGEMM.  C = act(alpha * A@B (+bias))   row-major, exact tile multiples.
// Batched via blockIdx.z with 2-level stride: z1 = z/divz, z2 = z%divz.
// ---------------------------------------------------------------------------
template <int BM, int BN, int BK, int TM, int TN, bool TRANSB>
__global__ __launch_bounds__(256) void gemm_kernel(
    const float* __restrict__ A, int lda,
    const float* __restrict__ B, int ldb,
    float* __restrict__ C, int ldc,
    int K, float alpha,
    const float* __restrict__ bias, int act,
    int divz, long sA1, long sA2, long sB1, long sB2, long sC1, long sC2)
{
    __shared__ float As[BK][BM + 4];
    __shared__ float Bs[BK][BN + 4];

    const int z = blockIdx.z;
    const int z1 = z / divz, z2 = z % divz;
    A += z1 * sA1 + z2 * sA2;
    B += z1 * sB1 + z2 * sB2;
    C += z1 * sC1 + z2 * sC2;

    const int tid = threadIdx.x;
    const int bm0 = blockIdx.y * BM;
    const int bn0 = blockIdx.x * BN;
    const int tx = tid % (BN / TN);
    const int ty = tid / (BN / TN);
    const int row0 = ty * TM, col0 = tx * TN;

    float acc[TM][TN];
#pragma unroll
    for (int i = 0; i < TM; i++)
#pragma unroll
        for (int j = 0; j < TN; j++) acc[i][j] = 0.0f;

    for (int k0 = 0; k0 < K; k0 += BK) {
        // Load A tile (BM x BK), store transposed
#pragma unroll
        for (int i = tid; i < BM * BK / 4; i += 256) {
            int r = i / (BK / 4);
            int kc = (i % (BK / 4)) * 4;
            float4 v = *(const float4*)(A + (size_t)(bm0 + r) * lda + k0 + kc);
            As[kc + 0][r] = v.x; As[kc + 1][r] = v.y;
            As[kc + 2][r] = v.z; As[kc + 3][r] = v.w;
        }
        if (!TRANSB) {
#pragma unroll
            for (int i = tid; i < BK * BN / 4; i += 256) {
                int kk = i / (BN / 4);
                int nc = (i % (BN / 4)) * 4;
                float4 v = *(const float4*)(B + (size_t)(k0 + kk) * ldb + bn0 + nc);
                *(float4*)&Bs[kk][nc] = v;
            }
        } else {
            // logical B[n][k] from storage B[n*ldb + k]
#pragma unroll
            for (int i = tid; i < BN * BK / 4; i += 256) {
                int n = i / (BK / 4);
                int kc = (i % (BK / 4)) * 4;
                float4 v = *(const float4*)(B + (size_t)(bn0 + n) * ldb + k0 + kc);
                Bs[kc + 0][n] = v.x; Bs[kc + 1][n] = v.y;
                Bs[kc + 2][n] = v.z; Bs[kc + 3][n] = v.w;
            }
        }
        __syncthreads();

#pragma unroll
        for (int kk = 0; kk < BK; kk++) {
            float a[TM], b[TN];
#pragma unroll
            for (int i = 0; i < TM; i += 4)
                *(float4*)&a[i] = *(const float4*)&As[kk][row0 + i];
#pragma unroll
            for (int j = 0; j < TN; j += 4)
                *(float4*)&b[j] = *(const float4*)&Bs[kk][col0 + j];
#pragma unroll
            for (int i = 0; i < TM; i++)
#pragma unroll
                for (int j = 0; j < TN; j++)
                    acc[i][j] += a[i] * b[j];
        }
        __syncthreads();
    }

    // Epilogue
#pragma unroll
    for (int i = 0; i < TM; i++) {
#pragma unroll
        for (int j = 0; j < TN; j++) {
            float v = acc[i][j] * alpha;
            if (bias) v += bias[bn0 + col0 + j];
            if (act) v = 0.5f * v * (1.0f + erff(v * 0.70710678118654752f));
            C[(size_t)(bm0 + row0 + i) * ldc + bn0 + col0 + j] = v;
        }
    }
}

// ---------------------------------------------------------------------------
// Masked softmax over rows of [B,H,S,Ll].  mode 0 = causal, mode 1 = padding.
// Masked entries in the reference get score -1e4; exp(-1e4 - max) == 0.0f in
// fp32, so zeroing them is bit-equivalent.
// ---------------------------------------------------------------------------
__global__ __launch_bounds__(256) void softmax_kernel(
    float* __restrict__ scores, int mode, const int* __restrict__ vlens)
{
    const int row = blockIdx.x;               // (b*H + h)*S + q
    const int q = row % Ss;
    const int b = row / (Hh * Ss);
    const int valid = (mode == 0) ? (q + 1) : vlens[b];

    float* p = scores + (size_t)row * Ll;
    const int t = threadIdx.x;
    float x0 = p[t];
    float x1 = p[t + 256];

    __shared__ float red[256];
    float m = -1e30f;
    if (t < valid) m = x0;
    if (t + 256 < valid) m = fmaxf(m, x1);
    red[t] = m; __syncthreads();
#pragma unroll
    for (int s = 128; s > 0; s >>= 1) {
        if (t < s) red[t] = fmaxf(red[t], red[t + s]);
        __syncthreads();
    }
    float mx = red[0];
    __syncthreads();

    float e0 = (t < valid) ? expf(x0 - mx) : 0.0f;
    float e1 = (t + 256 < valid) ? expf(x1 - mx) : 0.0f;
    red[t] = e0 + e1; __syncthreads();
#pragma unroll
    for (int s = 128; s > 0; s >>= 1) {
        if (t < s) red[t] += red[t + s];
        __syncthreads();
    }
    float inv = 1.0f / red[0];
    p[t] = e0 * inv;
    p[t + 256] = e1 * inv;
}

// ---------------------------------------------------------------------------
// out = LayerNorm(a + b) with weight w, bias bs.  One block per row of E=768.
// ---------------------------------------------------------------------------
__global__ __launch_bounds__(256) void add_ln_kernel(
    const float* __restrict__ a, const float* __restrict__ b,
    const float* __restrict__ w, const float* __restrict__ bs,
    float* __restrict__ out)
{
    const int row = blockIdx.x;
    const float* pa = a + (size_t)row * Ee;
    const float* pb = b + (size_t)row * Ee;
    const int t = threadIdx.x;

    float x[3];
    float s = 0.0f;
#pragma unroll
    for (int i = 0; i < 3; i++) {
        x[i] = pa[t + 256 * i] + pb[t + 256 * i];
        s += x[i];
    }
    __shared__ float red[256];
    red[t] = s; __syncthreads();
#pragma unroll
    for (int st = 128; st > 0; st >>= 1) {
        if (t < st) red[t] += red[t + st];
        __syncthreads();
    }
    float mean = red[0] * (1.0f / Ee);
    __syncthreads();

    float v = 0.0f;
#pragma unroll
    for (int i = 0; i < 3; i++) {
        float d = x[i] - mean;
        v += d * d;
    }
    red[t] = v; __syncthreads();
#pragma unroll
    for (int st = 128; st > 0; st >>= 1) {
        if (t < st) red[t] += red[t + st];
        __syncthreads();
    }
    float var = red[0] * (1.0f / Ee);
    float inv = rsqrtf(var + 1e-12f);

    float* po = out + (size_t)row * Ee;
#pragma unroll
    for (int i = 0; i < 3; i++) {
        int c = t + 256 * i;
        po[c] = w[c] * (x[i] - mean) * inv + bs[c];
    }
}

// ---------------------------------------------------------------------------
// Orchestration
// ---------------------------------------------------------------------------
extern "C" void kernel_launch(void* const* d_in, const int* in_sizes, int n_in,
                              void* d_out, int out_size)
{
    const float* X       = (const float*)d_in[0];
    const float* enc     = (const float*)d_in[1];
    const int*   vlens   = (const int*)  d_in[2];
    const float* w_kx1   = (const float*)d_in[3];
    const float* w_qx1   = (const float*)d_in[4];
    const float* proj1_w = (const float*)d_in[5];
    const float* proj1_b = (const float*)d_in[6];
    const float* ln1_w   = (const float*)d_in[7];
    const float* ln1_b   = (const float*)d_in[8];
    const float* w_kx2   = (const float*)d_in[9];
    const float* w_qx2   = (const float*)d_in[10];
    const float* proj2_w = (const float*)d_in[11];
    const float* proj2_b = (const float*)d_in[12];
    const float* ln2_w   = (const float*)d_in[13];
    const float* ln2_b   = (const float*)d_in[14];
    const float* ffn_w1  = (const float*)d_in[15];
    const float* ffn_b1  = (const float*)d_in[16];
    const float* ffn_w2  = (const float*)d_in[17];
    const float* ffn_b2  = (const float*)d_in[18];
    const float* ln3_w   = (const float*)d_in[19];
    const float* ln3_b   = (const float*)d_in[20];

    float *wp0, *wp1, *wp2, *wp3, *kx, *qx, *sc, *att, *tmp, *Y, *Z, *hid;
    cudaGetSymbolAddress((void**)&wp0, g_wp0);
    cudaGetSymbolAddress((void**)&wp1, g_wp1);
    cudaGetSymbolAddress((void**)&wp2, g_wp2);
    cudaGetSymbolAddress((void**)&wp3, g_wp3);
    cudaGetSymbolAddress((void**)&kx,  g_kx);
    cudaGetSymbolAddress((void**)&qx,  g_qx);
    cudaGetSymbolAddress((void**)&sc,  g_scores);
    cudaGetSymbolAddress((void**)&att, g_att);
    cudaGetSymbolAddress((void**)&tmp, g_tmp);
    cudaGetSymbolAddress((void**)&Y,   g_Y);
    cudaGetSymbolAddress((void**)&Z,   g_Z);
    cudaGetSymbolAddress((void**)&hid, g_hid);

    const int M  = Bb * Ss;            // 4096
    const long SE  = (long)Ss * Ee;    // 393216
    const long SL  = (long)Ss * Ll;    // 262144
    const long HSL = (long)Hh * SL;

    // GEMM configs
    auto* GEMM_L  = gemm_kernel<128, 128, 8, 8, 8, false>;  // large NN
    auto* GEMM_LT = gemm_kernel<128, 128, 8, 8, 8, true>;   // large NT (scores)
    auto* GEMM_AV = gemm_kernel<128, 64, 16, 8, 4, false>;  // N=64 (attn @ V)

    dim3 gridL(Ee / 128, M / 128, 1);        // [4096 x 768] x [768 x K]
    dim3 gridS(Ll / 128, Ss / 128, Bb * Hh); // scores, batched 96
    dim3 gridAV(1, Ss / 128, Bb * Hh);       // AV, batched 96

    // --- pack per-head weights into [E, H*HD] once per call -----------------
    int pblk = (Ee * Ee + 255) / 256;
    pack_w_kernel<<<pblk, 256>>>(w_kx1, wp0);
    pack_w_kernel<<<pblk, 256>>>(w_qx1, wp1);
    pack_w_kernel<<<pblk, 256>>>(w_kx2, wp2);
    pack_w_kernel<<<pblk, 256>>>(w_qx2, wp3);

    // ===================== Self-attention =====================
    GEMM_L<<<gridL, 256>>>(X, Ee, wp0, Ee, kx, Ee, Ee, 1.0f, nullptr, 0,
                           1, 0, 0, 0, 0, 0, 0);
    GEMM_L<<<gridL, 256>>>(X, Ee, wp1, Ee, qx, Ee, Ee, 1.0f, nullptr, 0,
                           1, 0, 0, 0, 0, 0, 0);
    // scores[b,h] = qx_slice @ kx_slice^T / 8
    GEMM_LT<<<gridS, 256>>>(qx, Ee, kx, Ee, sc, Ll, HDd, 0.125f, nullptr, 0,
                            Hh, SE, HDd, SE, HDd, HSL, SL);
    softmax_kernel<<<Bb * Hh * Ss, 256>>>(sc, 0, nullptr);
    // out[b,h] = probs @ kx_slice   (values are kx in the reference)
    GEMM_AV<<<gridAV, 256>>>(sc, Ll, kx, Ee, att, Ee, Ll, 1.0f, nullptr, 0,
                             Hh, HSL, SL, SE, HDd, SE, HDd);
    GEMM_L<<<gridL, 256>>>(att, Ee, proj1_w, Ee, tmp, Ee, Ee, 1.0f, proj1_b, 0,
                           1, 0, 0, 0, 0, 0, 0);
    add_ln_kernel<<<M, 256>>>(tmp, X, ln1_w, ln1_b, Y);

    // ===================== Cross-attention =====================
    GEMM_L<<<gridL, 256>>>(enc, Ee, wp2, Ee, kx, Ee, Ee, 1.0f, nullptr, 0,
                           1, 0, 0, 0, 0, 0, 0);
    GEMM_L<<<gridL, 256>>>(Y, Ee, wp3, Ee, qx, Ee, Ee, 1.0f, nullptr, 0,
                           1, 0, 0, 0, 0, 0, 0);
    GEMM_LT<<<gridS, 256>>>(qx, Ee, kx, Ee, sc, Ll, HDd, 0.125f, nullptr, 0,
                            Hh, SE, HDd, SE, HDd, HSL, SL);
    softmax_kernel<<<Bb * Hh * Ss, 256>>>(sc, 1, vlens);
    GEMM_AV<<<gridAV, 256>>>(sc, Ll, kx, Ee, att, Ee, Ll, 1.0f, nullptr, 0,
                             Hh, HSL, SL, SE, HDd, SE, HDd);
    GEMM_L<<<gridL, 256>>>(att, Ee, proj2_w, Ee, tmp, Ee, Ee, 1.0f, proj2_b, 0,
                           1, 0, 0, 0, 0, 0, 0);
    add_ln_kernel<<<M, 256>>>(tmp, Y, ln2_w, ln2_b, Z);

    // ===================== FFN =====================
    GEMM_L<<<gridL, 256>>>(Z, Ee, ffn_w1, Ee, hid, Ee, Ee, 1.0f, ffn_b1, 1,
                           1, 0, 0, 0, 0, 0, 0);
    GEMM_L<<<gridL, 256>>>(hid, Ee, ffn_w2, Ee, tmp, Ee, Ee, 1.0f, ffn_b2, 0,
                           1, 0, 0, 0, 0, 0, 0);
    add_ln_kernel<<<M, 256>>>(tmp, Z, ln3_w, ln3_b, (float*)d_out);
}

// round 2
// speedup vs baseline: 2.8541x; 2.8541x over previous
#include <cuda_runtime.h>
#include <math.h>
#include <stdint.h>

// Problem constants
#define Bb 8
#define Ss 512
#define Ll 512
#define Ee 768
#define Hh 12
#define HDd 64

// ---------------------------------------------------------------------------
// Scratch (device globals — no allocation allowed)
// ---------------------------------------------------------------------------
__device__ float g_wp0[Ee * Ee];                  // packed w_kx1 [n=h*64+d][k=e]
__device__ float g_wp1[Ee * Ee];
__device__ float g_wp2[Ee * Ee];
__device__ float g_wp3[Ee * Ee];
__device__ float g_pT1[Ee * Ee];                  // proj1_w^T  [n][k]
__device__ float g_pT2[Ee * Ee];
__device__ float g_fT1[Ee * Ee];                  // ffn_w1^T
__device__ float g_fT2[Ee * Ee];
__device__ float g_kx [Bb * Ss * Ee];             // keys  (concat-head layout)
__device__ float g_qx [Bb * Ss * Ee];             // queries
__device__ float g_kxT[Bb * Hh * HDd * Ss];       // kx transposed per (b,h): [d][l]
__device__ float g_scores[(size_t)Bb * Hh * Ss * Ll];
__device__ float g_att[Bb * Ss * Ee];
__device__ float g_tmp[Bb * Ss * Ee];
__device__ float g_Y  [Bb * Ss * Ee];
__device__ float g_Z  [Bb * Ss * Ee];
__device__ float g_hid[Bb * Ss * Ee];

// ---------------------------------------------------------------------------
// Helpers: fp32 -> bf16 hi/lo split (round-to-nearest-even)
// ---------------------------------------------------------------------------
__device__ __forceinline__ unsigned short f2bf(float f) {
    unsigned u = __float_as_uint(f);
    u += 0x7FFFu + ((u >> 16) & 1u);
    return (unsigned short)(u >> 16);
}
__device__ __forceinline__ float bf2f(unsigned short h) {
    return __uint_as_float(((unsigned)h) << 16);
}
// split two floats into packed-hi (2xbf16) and packed-lo (2xbf16) words
__device__ __forceinline__ void split2(float x, float y, unsigned &hi, unsigned &lo) {
    unsigned short hx = f2bf(x), hy = f2bf(y);
    unsigned short lx = f2bf(x - bf2f(hx)), ly = f2bf(y - bf2f(hy));
    hi = (unsigned)hx | ((unsigned)hy << 16);
    lo = (unsigned)lx | ((unsigned)ly << 16);
}

__device__ __forceinline__ void mma16816(float* c, const unsigned* a, unsigned b0, unsigned b1) {
    asm volatile(
        "mma.sync.aligned.m16n8k16.row.col.f32.bf16.bf16.f32 "
        "{%0,%1,%2,%3}, {%4,%5,%6,%7}, {%8,%9}, {%0,%1,%2,%3};\n"
        : "+f"(c[0]), "+f"(c[1]), "+f"(c[2]), "+f"(c[3])
        : "r"(a[0]), "r"(a[1]), "r"(a[2]), "r"(a[3]), "r"(b0), "r"(b1));
}

// ---------------------------------------------------------------------------
// Weight pack: w[h, e, d] -> wp[n = h*HD + d][k = e]
// ---------------------------------------------------------------------------
__global__ void pack_w_kernel(const float* __restrict__ w, float* __restrict__ wp) {
    int idx = blockIdx.x * blockDim.x + threadIdx.x;
    if (idx >= Ee * Ee) return;
    int n = idx / Ee, e = idx % Ee;
    int h = n / HDd, d = n % HDd;
    wp[idx] = w[((size_t)h * Ee + e) * HDd + d];
}

// ---------------------------------------------------------------------------
// 768x768 transpose: out[x][y] = in[y][x]
// ---------------------------------------------------------------------------
__global__ void transpose768(const float* __restrict__ in, float* __restrict__ out) {
    __shared__ float t[32][33];
    int x0 = blockIdx.x * 32, y0 = blockIdx.y * 32;
    int tx = threadIdx.x, ty = threadIdx.y;
#pragma unroll
    for (int i = 0; i < 32; i += 8)
        t[ty + i][tx] = in[(size_t)(y0 + ty + i) * Ee + x0 + tx];
    __syncthreads();
#pragma unroll
    for (int i = 0; i < 32; i += 8)
        out[(size_t)(x0 + ty + i) * Ee + y0 + tx] = t[tx][ty + i];
}

// ---------------------------------------------------------------------------
// kx [b, l, h*64+d] -> kxT [(b*H+h)*64 + d][l]
// ---------------------------------------------------------------------------
__global__ void transpose_kx_kernel(const float* __restrict__ kx, float* __restrict__ kxT) {
    __shared__ float t[32][33];
    int bh = blockIdx.z;
    int b = bh / Hh, h = bh % Hh;
    int l0 = blockIdx.x * 32, d0 = blockIdx.y * 32;
    int tx = threadIdx.x, ty = threadIdx.y;
#pragma unroll
    for (int i = 0; i < 32; i += 8)
        t[ty + i][tx] = kx[(size_t)(b * Ss + l0 + ty + i) * Ee + h * HDd + d0 + tx];
    __syncthreads();
#pragma unroll
    for (int i = 0; i < 32; i += 8)
        kxT[((size_t)bh * HDd + d0 + ty + i) * Ss + l0 + tx] = t[tx][ty + i];
}

// ---------------------------------------------------------------------------
// bf16x3 split-precision NT GEMM on tensor cores.
//   C[m][n] = act(alpha * sum_k A[m][k]*B[n][k] (+bias[n]))
// A fp32 row-major [m][k] (lda), B fp32 row-major [n][k] (ldb).
// Batched via blockIdx.z: z1 = z/divz, z2 = z%divz, base += z1*s1 + z2*s2.
// Requires: M%BM==0, N%BN==0, K%32==0.
// ---------------------------------------------------------------------------
template <int BM, int BN, int WM, int WN>
__global__ __launch_bounds__(256) void gemm_bf16x3(
    const float* __restrict__ A, int lda,
    const float* __restrict__ B, int ldb,
    float* __restrict__ C, int ldc,
    int K, float alpha, const float* __restrict__ bias, int act,
    int divz, long sA1, long sA2, long sB1, long sB2, long sC1, long sC2)
{
    constexpr int BK  = 32;
    constexpr int LDK = BK + 8;          // 40 shorts per row -> conflict-free frags
    constexpr int MF  = WM / 16;
    constexpr int NF  = WN / 8;
    constexpr int AP  = BM / 32;         // A rows loaded per pass (256 thr, 8 quads/row)
    constexpr int BP  = BN / 32;

    __shared__ __align__(16) unsigned short As_hi[BM * LDK];
    __shared__ __align__(16) unsigned short As_lo[BM * LDK];
    __shared__ __align__(16) unsigned short Bs_hi[BN * LDK];
    __shared__ __align__(16) unsigned short Bs_lo[BN * LDK];

    const int z = blockIdx.z;
    const int z1 = z / divz, z2 = z % divz;
    A += z1 * sA1 + z2 * sA2;
    B += z1 * sB1 + z2 * sB2;
    C += z1 * sC1 + z2 * sC2;

    const int tid  = threadIdx.x;
    const int warp = tid >> 5;
    const int lane = tid & 31;
    const int g    = lane >> 2;          // group id 0..7
    const int tig  = lane & 3;           // thread in group
    const int bm0  = blockIdx.y * BM;
    const int bn0  = blockIdx.x * BN;
    const int wm0  = (warp / (BN / WN)) * WM;
    const int wn0  = (warp % (BN / WN)) * WN;

    const int lq = tid & 7;              // float4-quad within a 32-float row
    const int lr = tid >> 3;             // 0..31

    float cacc[MF][NF][4];
#pragma unroll
    for (int mf = 0; mf < MF; mf++)
#pragma unroll
        for (int nf = 0; nf < NF; nf++)
#pragma unroll
            for (int i = 0; i < 4; i++) cacc[mf][nf][i] = 0.0f;

    float4 ra[AP], rb[BP];

    auto loadA = [&](int k0) {
#pragma unroll
        for (int p = 0; p < AP; p++)
            ra[p] = *(const float4*)(A + (size_t)(bm0 + lr + p * 32) * lda + k0 + lq * 4);
    };
    auto loadB = [&](int k0) {
#pragma unroll
        for (int p = 0; p < BP; p++)
            rb[p] = *(const float4*)(B + (size_t)(bn0 + lr + p * 32) * ldb + k0 + lq * 4);
    };
    auto stsAB = [&]() {
#pragma unroll
        for (int p = 0; p < AP; p++) {
            int off = (lr + p * 32) * LDK + lq * 4;
            unsigned h0, l0, h1, l1;
            split2(ra[p].x, ra[p].y, h0, l0);
            split2(ra[p].z, ra[p].w, h1, l1);
            *(unsigned*)&As_hi[off]     = h0;
            *(unsigned*)&As_hi[off + 2] = h1;
            *(unsigned*)&As_lo[off]     = l0;
            *(unsigned*)&As_lo[off + 2] = l1;
        }
#pragma unroll
        for (int p = 0; p < BP; p++) {
            int off = (lr + p * 32) * LDK + lq * 4;
            unsigned h0, l0, h1, l1;
            split2(rb[p].x, rb[p].y, h0, l0);
            split2(rb[p].z, rb[p].w, h1, l1);
            *(unsigned*)&Bs_hi[off]     = h0;
            *(unsigned*)&Bs_hi[off + 2] = h1;
            *(unsigned*)&Bs_lo[off]     = l0;
            *(unsigned*)&Bs_lo[off + 2] = l1;
        }
    };

    loadA(0); loadB(0);
    const int T = K / BK;

    for (int t = 0; t < T; t++) {
        stsAB();
        __syncthreads();
        if (t + 1 < T) { loadA((t + 1) * BK); loadB((t + 1) * BK); }

#pragma unroll
        for (int ks = 0; ks < 2; ks++) {
            unsigned bh[NF][2], bl[NF][2];
#pragma unroll
            for (int nf = 0; nf < NF; nf++) {
                int off = (wn0 + nf * 8 + g) * LDK + ks * 16 + tig * 2;
                bh[nf][0] = *(const unsigned*)&Bs_hi[off];
                bh[nf][1] = *(const unsigned*)&Bs_hi[off + 8];
                bl[nf][0] = *(const unsigned*)&Bs_lo[off];
                bl[nf][1] = *(const unsigned*)&Bs_lo[off + 8];
            }
#pragma unroll
            for (int mf = 0; mf < MF; mf++) {
                int off = (wm0 + mf * 16 + g) * LDK + ks * 16 + tig * 2;
                unsigned ah[4], al[4];
                ah[0] = *(const unsigned*)&As_hi[off];
                ah[1] = *(const unsigned*)&As_hi[off + 8 * LDK];
                ah[2] = *(const unsigned*)&As_hi[off + 8];
                ah[3] = *(const unsigned*)&As_hi[off + 8 * LDK + 8];
                al[0] = *(const unsigned*)&As_lo[off];
                al[1] = *(const unsigned*)&As_lo[off + 8 * LDK];
                al[2] = *(const unsigned*)&As_lo[off + 8];
                al[3] = *(const unsigned*)&As_lo[off + 8 * LDK + 8];
#pragma unroll
                for (int nf = 0; nf < NF; nf++) {
                    mma16816(cacc[mf][nf], ah, bh[nf][0], bh[nf][1]);   // hi*hi
                    mma16816(cacc[mf][nf], al, bh[nf][0], bh[nf][1]);   // lo*hi
                    mma16816(cacc[mf][nf], ah, bl[nf][0], bl[nf][1]);   // hi*lo
                }
            }
        }
        __syncthreads();
    }

    // Epilogue
#pragma unroll
    for (int mf = 0; mf < MF; mf++) {
#pragma unroll
        for (int nf = 0; nf < NF; nf++) {
            int row = bm0 + wm0 + mf * 16 + g;
            int col = bn0 + wn0 + nf * 8 + tig * 2;
            float b0 = 0.f, b1 = 0.f;
            if (bias) { b0 = bias[col]; b1 = bias[col + 1]; }
            float v0 = cacc[mf][nf][0] * alpha + b0;
            float v1 = cacc[mf][nf][1] * alpha + b1;
            float v2 = cacc[mf][nf][2] * alpha + b0;
            float v3 = cacc[mf][nf][3] * alpha + b1;
            if (act) {
                v0 = 0.5f * v0 * (1.0f + erff(v0 * 0.70710678118654752f));
                v1 = 0.5f * v1 * (1.0f + erff(v1 * 0.70710678118654752f));
                v2 = 0.5f * v2 * (1.0f + erff(v2 * 0.70710678118654752f));
                v3 = 0.5f * v3 * (1.0f + erff(v3 * 0.70710678118654752f));
            }
            *(float2*)&C[(size_t)row * ldc + col]       = make_float2(v0, v1);
            *(float2*)&C[(size_t)(row + 8) * ldc + col] = make_float2(v2, v3);
        }
    }
}

// ---------------------------------------------------------------------------
// Masked softmax over rows of [B,H,S,Ll].  mode 0 = causal, mode 1 = padding.
// ---------------------------------------------------------------------------
__global__ __launch_bounds__(256) void softmax_kernel(
    float* __restrict__ scores, int mode, const int* __restrict__ vlens)
{
    const int row = blockIdx.x;               // (b*H + h)*S + q
    const int q = row % Ss;
    const int b = row / (Hh * Ss);
    const int valid = (mode == 0) ? (q + 1) : vlens[b];

    float* p = scores + (size_t)row * Ll;
    const int t = threadIdx.x;
    float x0 = p[t];
    float x1 = p[t + 256];

    __shared__ float red[256];
    float m = -1e30f;
    if (t < valid) m = x0;
    if (t + 256 < valid) m = fmaxf(m, x1);
    red[t] = m; __syncthreads();
#pragma unroll
    for (int s = 128; s > 0; s >>= 1) {
        if (t < s) red[t] = fmaxf(red[t], red[t + s]);
        __syncthreads();
    }
    float mx = red[0];
    __syncthreads();

    float e0 = (t < valid) ? expf(x0 - mx) : 0.0f;
    float e1 = (t + 256 < valid) ? expf(x1 - mx) : 0.0f;
    red[t] = e0 + e1; __syncthreads();
#pragma unroll
    for (int s = 128; s > 0; s >>= 1) {
        if (t < s) red[t] += red[t + s];
        __syncthreads();
    }
    float inv = 1.0f / red[0];
    p[t] = e0 * inv;
    p[t + 256] = e1 * inv;
}

// ---------------------------------------------------------------------------
// out = LayerNorm(a + b)
// ---------------------------------------------------------------------------
__global__ __launch_bounds__(256) void add_ln_kernel(
    const float* __restrict__ a, const float* __restrict__ b,
    const float* __restrict__ w, const float* __restrict__ bs,
    float* __restrict__ out)
{
    const int row = blockIdx.x;
    const float* pa = a + (size_t)row * Ee;
    const float* pb = b + (size_t)row * Ee;
    const int t = threadIdx.x;

    float x[3];
    float s = 0.0f;
#pragma unroll
    for (int i = 0; i < 3; i++) {
        x[i] = pa[t + 256 * i] + pb[t + 256 * i];
        s += x[i];
    }
    __shared__ float red[256];
    red[t] = s; __syncthreads();
#pragma unroll
    for (int st = 128; st > 0; st >>= 1) {
        if (t < st) red[t] += red[t + st];
        __syncthreads();
    }
    float mean = red[0] * (1.0f / Ee);
    __syncthreads();

    float v = 0.0f;
#pragma unroll
    for (int i = 0; i < 3; i++) {
        float d = x[i] - mean;
        v += d * d;
    }
    red[t] = v; __syncthreads();
#pragma unroll
    for (int st = 128; st > 0; st >>= 1) {
        if (t < st) red[t] += red[t + st];
        __syncthreads();
    }
    float var = red[0] * (1.0f / Ee);
    float inv = rsqrtf(var + 1e-12f);

    float* po = out + (size_t)row * Ee;
#pragma unroll
    for (int i = 0; i < 3; i++) {
        int c = t + 256 * i;
        po[c] = w[c] * (x[i] - mean) * inv + bs[c];
    }
}

// ---------------------------------------------------------------------------
// Orchestration
// ---------------------------------------------------------------------------
extern "C" void kernel_launch(void* const* d_in, const int* in_sizes, int n_in,
                              void* d_out, int out_size)
{
    const float* X       = (const float*)d_in[0];
    const float* enc     = (const float*)d_in[1];
    const int*   vlens   = (const int*)  d_in[2];
    const float* w_kx1   = (const float*)d_in[3];
    const float* w_qx1   = (const float*)d_in[4];
    const float* proj1_w = (const float*)d_in[5];
    const float* proj1_b = (const float*)d_in[6];
    const float* ln1_w   = (const float*)d_in[7];
    const float* ln1_b   = (const float*)d_in[8];
    const float* w_kx2   = (const float*)d_in[9];
    const float* w_qx2   = (const float*)d_in[10];
    const float* proj2_w = (const float*)d_in[11];
    const float* proj2_b = (const float*)d_in[12];
    const float* ln2_w   = (const float*)d_in[13];
    const float* ln2_b   = (const float*)d_in[14];
    const float* ffn_w1  = (const float*)d_in[15];
    const float* ffn_b1  = (const float*)d_in[16];
    const float* ffn_w2  = (const float*)d_in[17];
    const float* ffn_b2  = (const float*)d_in[18];
    const float* ln3_w   = (const float*)d_in[19];
    const float* ln3_b   = (const float*)d_in[20];

    float *wp0, *wp1, *wp2, *wp3, *pT1, *pT2, *fT1, *fT2;
    float *kx, *qx, *kxT, *sc, *att, *tmp, *Y, *Z, *hid;
    cudaGetSymbolAddress((void**)&wp0, g_wp0);
    cudaGetSymbolAddress((void**)&wp1, g_wp1);
    cudaGetSymbolAddress((void**)&wp2, g_wp2);
    cudaGetSymbolAddress((void**)&wp3, g_wp3);
    cudaGetSymbolAddress((void**)&pT1, g_pT1);
    cudaGetSymbolAddress((void**)&pT2, g_pT2);
    cudaGetSymbolAddress((void**)&fT1, g_fT1);
    cudaGetSymbolAddress((void**)&fT2, g_fT2);
    cudaGetSymbolAddress((void**)&kx,  g_kx);
    cudaGetSymbolAddress((void**)&qx,  g_qx);
    cudaGetSymbolAddress((void**)&kxT, g_kxT);
    cudaGetSymbolAddress((void**)&sc,  g_scores);
    cudaGetSymbolAddress((void**)&att, g_att);
    cudaGetSymbolAddress((void**)&tmp, g_tmp);
    cudaGetSymbolAddress((void**)&Y,   g_Y);
    cudaGetSymbolAddress((void**)&Z,   g_Z);
    cudaGetSymbolAddress((void**)&hid, g_hid);

    const int  M   = Bb * Ss;           // 4096
    const long SE  = (long)Ss * Ee;
    const long SL  = (long)Ss * Ll;
    const long HSL = (long)Hh * SL;
    const long HDS = (long)HDd * Ss;    // kxT per-head stride
    const long HHDS = (long)Hh * HDS;   // kxT per-batch stride

    auto* G_PROJ = gemm_bf16x3<128, 128, 64, 32>;   // big NT GEMMs
    auto* G_SC   = gemm_bf16x3<128, 128, 64, 32>;   // scores
    auto* G_AV   = gemm_bf16x3<128, 64, 32, 32>;    // attn @ V (N=64)

    dim3 gridL(Ee / 128, M / 128, 1);
    dim3 gridS(Ll / 128, Ss / 128, Bb * Hh);
    dim3 gridAV(1, Ss / 128, Bb * Hh);
    dim3 tb(32, 8);
    dim3 gridT768(Ee / 32, Ee / 32, 1);
    dim3 gridTK(Ss / 32, HDd / 32, Bb * Hh);

    // --- per-call weight prep ----------------------------------------------
    int pblk = (Ee * Ee + 255) / 256;
    pack_w_kernel<<<pblk, 256>>>(w_kx1, wp0);
    pack_w_kernel<<<pblk, 256>>>(w_qx1, wp1);
    pack_w_kernel<<<pblk, 256>>>(w_kx2, wp2);
    pack_w_kernel<<<pblk, 256>>>(w_qx2, wp3);
    transpose768<<<gridT768, tb>>>(proj1_w, pT1);
    transpose768<<<gridT768, tb>>>(proj2_w, pT2);
    transpose768<<<gridT768, tb>>>(ffn_w1, fT1);
    transpose768<<<gridT768, tb>>>(ffn_w2, fT2);

    // ===================== Self-attention =====================
    G_PROJ<<<gridL, 256>>>(X, Ee, wp0, Ee, kx, Ee, Ee, 1.0f, nullptr, 0,
                           1, 0, 0, 0, 0, 0, 0);
    G_PROJ<<<gridL, 256>>>(X, Ee, wp1, Ee, qx, Ee, Ee, 1.0f, nullptr, 0,
                           1, 0, 0, 0, 0, 0, 0);
    transpose_kx_kernel<<<gridTK, tb>>>(kx, kxT);
    G_SC<<<gridS, 256>>>(qx, Ee, kx, Ee, sc, Ll, HDd, 0.125f, nullptr, 0,
                         Hh, SE, HDd, SE, HDd, HSL, SL);
    softmax_kernel<<<Bb * Hh * Ss, 256>>>(sc, 0, nullptr);
    G_AV<<<gridAV, 256>>>(sc, Ll, kxT, Ss, att, Ee, Ss, 1.0f, nullptr, 0,
                          Hh, HSL, SL, HHDS, HDS, SE, HDd);
    G_PROJ<<<gridL, 256>>>(att, Ee, pT1, Ee, tmp, Ee, Ee, 1.0f, proj1_b, 0,
                           1, 0, 0, 0, 0, 0, 0);
    add_ln_kernel<<<M, 256>>>(tmp, X, ln1_w, ln1_b, Y);

    // ===================== Cross-attention =====================
    G_PROJ<<<gridL, 256>>>(enc, Ee, wp2, Ee, kx, Ee, Ee, 1.0f, nullptr, 0,
                           1, 0, 0, 0, 0, 0, 0);
    G_PROJ<<<gridL, 256>>>(Y, Ee, wp3, Ee, qx, Ee, Ee, 1.0f, nullptr, 0,
                           1, 0, 0, 0, 0, 0, 0);
    transpose_kx_kernel<<<gridTK, tb>>>(kx, kxT);
    G_SC<<<gridS, 256>>>(qx, Ee, kx, Ee, sc, Ll, HDd, 0.125f, nullptr, 0,
                         Hh, SE, HDd, SE, HDd, HSL, SL);
    softmax_kernel<<<Bb * Hh * Ss, 256>>>(sc, 1, vlens);
    G_AV<<<gridAV, 256>>>(sc, Ll, kxT, Ss, att, Ee, Ss, 1.0f, nullptr, 0,
                          Hh, HSL, SL, HHDS, HDS, SE, HDd);
    G_PROJ<<<gridL, 256>>>(att, Ee, pT2, Ee, tmp, Ee, Ee, 1.0f, proj2_b, 0,
                           1, 0, 0, 0, 0, 0, 0);
    add_ln_kernel<<<M, 256>>>(tmp, Y, ln2_w, ln2_b, Z);

    // ===================== FFN =====================
    G_PROJ<<<gridL, 256>>>(Z, Ee, fT1, Ee, hid, Ee, Ee, 1.0f, ffn_b1, 1,
                           1, 0, 0, 0, 0, 0, 0);
    G_PROJ<<<gridL, 256>>>(hid, Ee, fT2, Ee, tmp, Ee, Ee, 1.0f, ffn_b2, 0,
                           1, 0, 0, 0, 0, 0, 0);
    add_ln_kernel<<<M, 256>>>(tmp, Z, ln3_w, ln3_b, (float*)d_out);
}

// round 3
// speedup vs baseline: 3.0771x; 1.0781x over previous
#include <cuda_runtime.h>
#include <cuda_bf16.h>
#include <math.h>
#include <stdint.h>

// Problem constants
#define Bb 8
#define Ss 512
#define Ll 512
#define Ee 768
#define Hh 12
#define HDd 64

#define NELE (Bb * Ss * Ee)                       // 3145728
#define NSC  ((size_t)Bb * Hh * Ss * Ll)          // 25165824

// ---------------------------------------------------------------------------
// Scratch (device globals — no allocation allowed)
// ---------------------------------------------------------------------------
__device__ float g_kx [NELE];
__device__ float g_tmp[NELE];
__device__ float g_Y  [NELE];
__device__ float g_Z  [NELE];
__device__ float g_sc [NSC];

__device__ unsigned short g_Xh[NELE],   g_Xl[NELE];
__device__ unsigned short g_ench[NELE], g_encl[NELE];
__device__ unsigned short g_kxh[NELE],  g_kxl[NELE];
__device__ unsigned short g_qxh[NELE],  g_qxl[NELE];
__device__ unsigned short g_kxTh[NELE], g_kxTl[NELE];     // [(b*H+h)*64+d][l]
__device__ unsigned short g_atth[NELE], g_attl[NELE];
__device__ unsigned short g_hidh[NELE], g_hidl[NELE];
__device__ unsigned short g_Yh[NELE],   g_Yl[NELE];
__device__ unsigned short g_Zh[NELE],   g_Zl[NELE];
__device__ unsigned short g_sch[NSC],   g_scl[NSC];
__device__ unsigned short g_wp0h[Ee*Ee], g_wp0l[Ee*Ee];
__device__ unsigned short g_wp1h[Ee*Ee], g_wp1l[Ee*Ee];
__device__ unsigned short g_wp2h[Ee*Ee], g_wp2l[Ee*Ee];
__device__ unsigned short g_wp3h[Ee*Ee], g_wp3l[Ee*Ee];
__device__ unsigned short g_pT1h[Ee*Ee], g_pT1l[Ee*Ee];
__device__ unsigned short g_pT2h[Ee*Ee], g_pT2l[Ee*Ee];
__device__ unsigned short g_fT1h[Ee*Ee], g_fT1l[Ee*Ee];
__device__ unsigned short g_fT2h[Ee*Ee], g_fT2l[Ee*Ee];

// ---------------------------------------------------------------------------
// fp32 <-> bf16 hi/lo split helpers
// ---------------------------------------------------------------------------
__device__ __forceinline__ unsigned short f2bf(float f) {
    unsigned u = __float_as_uint(f);
    u += 0x7FFFu + ((u >> 16) & 1u);
    return (unsigned short)(u >> 16);
}
__device__ __forceinline__ float bf2f(unsigned short h) {
    return __uint_as_float(((unsigned)h) << 16);
}
__device__ __forceinline__ void split1(float x, unsigned short &h, unsigned short &l) {
    h = f2bf(x);
    l = f2bf(x - bf2f(h));
}
__device__ __forceinline__ void split2(float x, float y, unsigned &hi, unsigned &lo) {
    unsigned short hx, lx, hy, ly;
    split1(x, hx, lx); split1(y, hy, ly);
    hi = (unsigned)hx | ((unsigned)hy << 16);
    lo = (unsigned)lx | ((unsigned)ly << 16);
}

__device__ __forceinline__ void mma16816(float* c, const unsigned* a, unsigned b0, unsigned b1) {
    asm volatile(
        "mma.sync.aligned.m16n8k16.row.col.f32.bf16.bf16.f32 "
        "{%0,%1,%2,%3}, {%4,%5,%6,%7}, {%8,%9}, {%0,%1,%2,%3};\n"
        : "+f"(c[0]), "+f"(c[1]), "+f"(c[2]), "+f"(c[3])
        : "r"(a[0]), "r"(a[1]), "r"(a[2]), "r"(a[3]), "r"(b0), "r"(b1));
}

// ---------------------------------------------------------------------------
// Prep kernels
// ---------------------------------------------------------------------------
// w[h, e, d] -> hi/lo [n = h*HD + d][k = e]
__global__ void pack_w_split(const float* __restrict__ w,
                             unsigned short* __restrict__ oh,
                             unsigned short* __restrict__ ol) {
    int idx = blockIdx.x * blockDim.x + threadIdx.x;
    if (idx >= Ee * Ee) return;
    int n = idx / Ee, e = idx % Ee;
    int h = n / HDd, d = n % HDd;
    split1(w[((size_t)h * Ee + e) * HDd + d], oh[idx], ol[idx]);
}

// fp32[n] -> hi[n], lo[n]  (n % 4 == 0)
__global__ void split_kernel(const float* __restrict__ in,
                             unsigned short* __restrict__ oh,
                             unsigned short* __restrict__ ol, int n4) {
    int i = blockIdx.x * blockDim.x + threadIdx.x;
    if (i >= n4) return;
    float4 v = ((const float4*)in)[i];
    unsigned h0, l0, h1, l1;
    split2(v.x, v.y, h0, l0);
    split2(v.z, v.w, h1, l1);
    ((uint2*)oh)[i] = make_uint2(h0, h1);
    ((uint2*)ol)[i] = make_uint2(l0, l1);
}

// 768x768 transpose + split: out[x][y] = in[y][x]
__global__ void transpose768_split(const float* __restrict__ in,
                                   unsigned short* __restrict__ oh,
                                   unsigned short* __restrict__ ol) {
    __shared__ float t[32][33];
    int x0 = blockIdx.x * 32, y0 = blockIdx.y * 32;
    int tx = threadIdx.x, ty = threadIdx.y;
#pragma unroll
    for (int i = 0; i < 32; i += 8)
        t[ty + i][tx] = in[(size_t)(y0 + ty + i) * Ee + x0 + tx];
    __syncthreads();
#pragma unroll
    for (int i = 0; i < 32; i += 8) {
        size_t o = (size_t)(x0 + ty + i) * Ee + y0 + tx;
        split1(t[tx][ty + i], oh[o], ol[o]);
    }
}

// kx fp32 [b, l, h*64+d] -> hi/lo [(b*H+h)*64 + d][l]
__global__ void transpose_kx_split(const float* __restrict__ kx,
                                   unsigned short* __restrict__ oh,
                                   unsigned short* __restrict__ ol) {
    __shared__ float t[32][33];
    int bh = blockIdx.z;
    int b = bh / Hh, h = bh % Hh;
    int l0 = blockIdx.x * 32, d0 = blockIdx.y * 32;
    int tx = threadIdx.x, ty = threadIdx.y;
#pragma unroll
    for (int i = 0; i < 32; i += 8)
        t[ty + i][tx] = kx[(size_t)(b * Ss + l0 + ty + i) * Ee + h * HDd + d0 + tx];
    __syncthreads();
#pragma unroll
    for (int i = 0; i < 32; i += 8) {
        size_t o = ((size_t)bh * HDd + d0 + ty + i) * Ss + l0 + tx;
        split1(t[tx][ty + i], oh[o], ol[o]);
    }
}

// ---------------------------------------------------------------------------
// Pre-split bf16x3 NT GEMM, cp.async double-buffered.
//   C = act(alpha * A@B^T (+bias))
// A hi/lo [m][k] (lda), B hi/lo [n][k] (ldb), outputs: fp32 Cf and/or hi/lo.
// Requires M%BM==0, N%BN==0, K%32==0, all row strides 16B-aligned.
// ---------------------------------------------------------------------------
template <int BM, int BN, int WM, int WN>
__global__ __launch_bounds__(256) void gemm_pre(
    const unsigned short* __restrict__ Ah, const unsigned short* __restrict__ Al, int lda,
    const unsigned short* __restrict__ Bh, const unsigned short* __restrict__ Bl, int ldb,
    float* __restrict__ Cf, unsigned short* __restrict__ Chi, unsigned short* __restrict__ Clo,
    int ldc, int K, float alpha, const float* __restrict__ bias, int act,
    int divz, long sA1, long sA2, long sB1, long sB2, long sC1, long sC2)
{
    constexpr int BK = 32, BKp = 40;                  // 80B rows (16B-aligned)
    constexpr int ASZ = BM * BKp, BSZ = BN * BKp;
    constexpr int STG = 2 * (ASZ + BSZ);              // shorts per stage
    constexpr int MF = WM / 16, NF = WN / 8;
    extern __shared__ __align__(16) unsigned short smx[];

    const int z = blockIdx.z;
    const int z1 = z / divz, z2 = z % divz;
    const long aoff = z1 * sA1 + z2 * sA2;
    const long boff = z1 * sB1 + z2 * sB2;
    const long coff = z1 * sC1 + z2 * sC2;
    Ah += aoff; Al += aoff; Bh += boff; Bl += boff;

    const int tid = threadIdx.x;
    const int warp = tid >> 5, lane = tid & 31;
    const int g = lane >> 2, tig = lane & 3;
    const int bm0 = blockIdx.y * BM, bn0 = blockIdx.x * BN;
    const int wm0 = (warp / (BN / WN)) * WM;
    const int wn0 = (warp % (BN / WN)) * WN;

    float cacc[MF][NF][4];
#pragma unroll
    for (int mf = 0; mf < MF; mf++)
#pragma unroll
        for (int nf = 0; nf < NF; nf++)
#pragma unroll
            for (int i = 0; i < 4; i++) cacc[mf][nf][i] = 0.0f;

    auto load_stage = [&](int s, int k0) {
        unsigned short* base = smx + s * STG;
#pragma unroll
        for (int arr = 0; arr < 2; arr++) {
            unsigned short* d0 = base + arr * ASZ;
            const unsigned short* s0 = arr ? Al : Ah;
            for (int c = tid; c < BM * 4; c += 256) {
                int r = c >> 2, ch = c & 3;
                uint32_t da = (uint32_t)__cvta_generic_to_shared(d0 + r * BKp + ch * 8);
                const void* sa = s0 + (size_t)(bm0 + r) * lda + k0 + ch * 8;
                asm volatile("cp.async.cg.shared.global [%0], [%1], 16;\n" :: "r"(da), "l"(sa));
            }
        }
#pragma unroll
        for (int arr = 0; arr < 2; arr++) {
            unsigned short* d0 = base + 2 * ASZ + arr * BSZ;
            const unsigned short* s0 = arr ? Bl : Bh;
            for (int c = tid; c < BN * 4; c += 256) {
                int r = c >> 2, ch = c & 3;
                uint32_t da = (uint32_t)__cvta_generic_to_shared(d0 + r * BKp + ch * 8);
                const void* sa = s0 + (size_t)(bn0 + r) * ldb + k0 + ch * 8;
                asm volatile("cp.async.cg.shared.global [%0], [%1], 16;\n" :: "r"(da), "l"(sa));
            }
        }
        asm volatile("cp.async.commit_group;\n");
    };

    const int T = K / BK;
    load_stage(0, 0);

    for (int t = 0; t < T; t++) {
        if (t + 1 < T) {
            load_stage((t + 1) & 1, (t + 1) * BK);
            asm volatile("cp.async.wait_group 1;\n");
        } else {
            asm volatile("cp.async.wait_group 0;\n");
        }
        __syncthreads();

        const unsigned short* As_h = smx + (t & 1) * STG;
        const unsigned short* As_l = As_h + ASZ;
        const unsigned short* Bs_h = As_h + 2 * ASZ;
        const unsigned short* Bs_l = Bs_h + BSZ;

#pragma unroll
        for (int ks = 0; ks < 2; ks++) {
            unsigned bh[NF][2], bl[NF][2];
#pragma unroll
            for (int nf = 0; nf < NF; nf++) {
                int off = (wn0 + nf * 8 + g) * BKp + ks * 16 + tig * 2;
                bh[nf][0] = *(const unsigned*)&Bs_h[off];
                bh[nf][1] = *(const unsigned*)&Bs_h[off + 8];
                bl[nf][0] = *(const unsigned*)&Bs_l[off];
                bl[nf][1] = *(const unsigned*)&Bs_l[off + 8];
            }
#pragma unroll
            for (int mf = 0; mf < MF; mf++) {
                int off = (wm0 + mf * 16 + g) * BKp + ks * 16 + tig * 2;
                unsigned ah[4], al[4];
                ah[0] = *(const unsigned*)&As_h[off];
                ah[1] = *(const unsigned*)&As_h[off + 8 * BKp];
                ah[2] = *(const unsigned*)&As_h[off + 8];
                ah[3] = *(const unsigned*)&As_h[off + 8 * BKp + 8];
                al[0] = *(const unsigned*)&As_l[off];
                al[1] = *(const unsigned*)&As_l[off + 8 * BKp];
                al[2] = *(const unsigned*)&As_l[off + 8];
                al[3] = *(const unsigned*)&As_l[off + 8 * BKp + 8];
#pragma unroll
                for (int nf = 0; nf < NF; nf++) {
                    mma16816(cacc[mf][nf], ah, bh[nf][0], bh[nf][1]);   // hi*hi
                    mma16816(cacc[mf][nf], al, bh[nf][0], bh[nf][1]);   // lo*hi
                    mma16816(cacc[mf][nf], ah, bl[nf][0], bl[nf][1]);   // hi*lo
                }
            }
        }
        __syncthreads();
    }

    // Epilogue
#pragma unroll
    for (int mf = 0; mf < MF; mf++) {
#pragma unroll
        for (int nf = 0; nf < NF; nf++) {
            int row = bm0 + wm0 + mf * 16 + g;
            int col = bn0 + wn0 + nf * 8 + tig * 2;
            float b0 = 0.f, b1 = 0.f;
            if (bias) { b0 = bias[col]; b1 = bias[col + 1]; }
            float v0 = cacc[mf][nf][0] * alpha + b0;
            float v1 = cacc[mf][nf][1] * alpha + b1;
            float v2 = cacc[mf][nf][2] * alpha + b0;
            float v3 = cacc[mf][nf][3] * alpha + b1;
            if (act) {
                v0 = 0.5f * v0 * (1.0f + erff(v0 * 0.70710678118654752f));
                v1 = 0.5f * v1 * (1.0f + erff(v1 * 0.70710678118654752f));
                v2 = 0.5f * v2 * (1.0f + erff(v2 * 0.70710678118654752f));
                v3 = 0.5f * v3 * (1.0f + erff(v3 * 0.70710678118654752f));
            }
            size_t o0 = coff + (size_t)row * ldc + col;
            size_t o1 = coff + (size_t)(row + 8) * ldc + col;
            if (Cf) {
                *(float2*)&Cf[o0] = make_float2(v0, v1);
                *(float2*)&Cf[o1] = make_float2(v2, v3);
            }
            if (Chi) {
                unsigned h0, l0, h1, l1;
                split2(v0, v1, h0, l0);
                split2(v2, v3, h1, l1);
                *(unsigned*)&Chi[o0] = h0; *(unsigned*)&Clo[o0] = l0;
                *(unsigned*)&Chi[o1] = h1; *(unsigned*)&Clo[o1] = l1;
            }
        }
    }
}

// ---------------------------------------------------------------------------
// Masked softmax: fp32 scores in, hi/lo bf16 probs out.
// mode 0 = causal, mode 1 = key padding.
// ---------------------------------------------------------------------------
__global__ __launch_bounds__(256) void softmax_split_kernel(
    const float* __restrict__ scores,
    unsigned short* __restrict__ ph, unsigned short* __restrict__ pl,
    int mode, const int* __restrict__ vlens)
{
    const int row = blockIdx.x;               // (b*H + h)*S + q
    const int q = row % Ss;
    const int b = row / (Hh * Ss);
    const int valid = (mode == 0) ? (q + 1) : vlens[b];

    const float* p = scores + (size_t)row * Ll;
    const int t = threadIdx.x;
    float x0 = p[t];
    float x1 = p[t + 256];

    __shared__ float red[256];
    float m = -1e30f;
    if (t < valid) m = x0;
    if (t + 256 < valid) m = fmaxf(m, x1);
    red[t] = m; __syncthreads();
#pragma unroll
    for (int s = 128; s > 0; s >>= 1) {
        if (t < s) red[t] = fmaxf(red[t], red[t + s]);
        __syncthreads();
    }
    float mx = red[0];
    __syncthreads();

    float e0 = (t < valid) ? expf(x0 - mx) : 0.0f;
    float e1 = (t + 256 < valid) ? expf(x1 - mx) : 0.0f;
    red[t] = e0 + e1; __syncthreads();
#pragma unroll
    for (int s = 128; s > 0; s >>= 1) {
        if (t < s) red[t] += red[t + s];
        __syncthreads();
    }
    float inv = 1.0f / red[0];
    size_t o = (size_t)row * Ll;
    split1(e0 * inv, ph[o + t], pl[o + t]);
    split1(e1 * inv, ph[o + t + 256], pl[o + t + 256]);
}

// ---------------------------------------------------------------------------
// out = LayerNorm(a + b); optional hi/lo bf16 copy of out.
// ---------------------------------------------------------------------------
__global__ __launch_bounds__(256) void add_ln_kernel(
    const float* __restrict__ a, const float* __restrict__ b,
    const float* __restrict__ w, const float* __restrict__ bs,
    float* __restrict__ out,
    unsigned short* __restrict__ oh, unsigned short* __restrict__ ol)
{
    const int row = blockIdx.x;
    const float* pa = a + (size_t)row * Ee;
    const float* pb = b + (size_t)row * Ee;
    const int t = threadIdx.x;

    float x[3];
    float s = 0.0f;
#pragma unroll
    for (int i = 0; i < 3; i++) {
        x[i] = pa[t + 256 * i] + pb[t + 256 * i];
        s += x[i];
    }
    __shared__ float red[256];
    red[t] = s; __syncthreads();
#pragma unroll
    for (int st = 128; st > 0; st >>= 1) {
        if (t < st) red[t] += red[t + st];
        __syncthreads();
    }
    float mean = red[0] * (1.0f / Ee);
    __syncthreads();

    float v = 0.0f;
#pragma unroll
    for (int i = 0; i < 3; i++) {
        float d = x[i] - mean;
        v += d * d;
    }
    red[t] = v; __syncthreads();
#pragma unroll
    for (int st = 128; st > 0; st >>= 1) {
        if (t < st) red[t] += red[t + st];
        __syncthreads();
    }
    float var = red[0] * (1.0f / Ee);
    float inv = rsqrtf(var + 1e-12f);

#pragma unroll
    for (int i = 0; i < 3; i++) {
        int c = t + 256 * i;
        float o = w[c] * (x[i] - mean) * inv + bs[c];
        size_t off = (size_t)row * Ee + c;
        out[off] = o;
        if (oh) split1(o, oh[off], ol[off]);
    }
}

// ---------------------------------------------------------------------------
// Orchestration
// ---------------------------------------------------------------------------
extern "C" void kernel_launch(void* const* d_in, const int* in_sizes, int n_in,
                              void* d_out, int out_size)
{
    const float* X       = (const float*)d_in[0];
    const float* enc     = (const float*)d_in[1];
    const int*   vlens   = (const int*)  d_in[2];
    const float* w_kx1   = (const float*)d_in[3];
    const float* w_qx1   = (const float*)d_in[4];
    const float* proj1_w = (const float*)d_in[5];
    const float* proj1_b = (const float*)d_in[6];
    const float* ln1_w   = (const float*)d_in[7];
    const float* ln1_b   = (const float*)d_in[8];
    const float* w_kx2   = (const float*)d_in[9];
    const float* w_qx2   = (const float*)d_in[10];
    const float* proj2_w = (const float*)d_in[11];
    const float* proj2_b = (const float*)d_in[12];
    const float* ln2_w   = (const float*)d_in[13];
    const float* ln2_b   = (const float*)d_in[14];
    const float* ffn_w1  = (const float*)d_in[15];
    const float* ffn_b1  = (const float*)d_in[16];
    const float* ffn_w2  = (const float*)d_in[17];
    const float* ffn_b2  = (const float*)d_in[18];
    const float* ln3_w   = (const float*)d_in[19];
    const float* ln3_b   = (const float*)d_in[20];

#define SYM(p, s) cudaGetSymbolAddress((void**)&p, s)
    float *kx, *tmp, *Y, *Z, *sc;
    unsigned short *Xh,*Xl,*ench,*encl,*kxh,*kxl,*qxh,*qxl,*kxTh,*kxTl;
    unsigned short *atth,*attl,*hidh,*hidl,*Yh,*Yl,*Zh,*Zl,*sch,*scl;
    unsigned short *wp0h,*wp0l,*wp1h,*wp1l,*wp2h,*wp2l,*wp3h,*wp3l;
    unsigned short *pT1h,*pT1l,*pT2h,*pT2l,*fT1h,*fT1l,*fT2h,*fT2l;
    SYM(kx, g_kx); SYM(tmp, g_tmp); SYM(Y, g_Y); SYM(Z, g_Z); SYM(sc, g_sc);
    SYM(Xh, g_Xh); SYM(Xl, g_Xl); SYM(ench, g_ench); SYM(encl, g_encl);
    SYM(kxh, g_kxh); SYM(kxl, g_kxl); SYM(qxh, g_qxh); SYM(qxl, g_qxl);
    SYM(kxTh, g_kxTh); SYM(kxTl, g_kxTl);
    SYM(atth, g_atth); SYM(attl, g_attl); SYM(hidh, g_hidh); SYM(hidl, g_hidl);
    SYM(Yh, g_Yh); SYM(Yl, g_Yl); SYM(Zh, g_Zh); SYM(Zl, g_Zl);
    SYM(sch, g_sch); SYM(scl, g_scl);
    SYM(wp0h, g_wp0h); SYM(wp0l, g_wp0l); SYM(wp1h, g_wp1h); SYM(wp1l, g_wp1l);
    SYM(wp2h, g_wp2h); SYM(wp2l, g_wp2l); SYM(wp3h, g_wp3h); SYM(wp3l, g_wp3l);
    SYM(pT1h, g_pT1h); SYM(pT1l, g_pT1l); SYM(pT2h, g_pT2h); SYM(pT2l, g_pT2l);
    SYM(fT1h, g_fT1h); SYM(fT1l, g_fT1l); SYM(fT2h, g_fT2h); SYM(fT2l, g_fT2l);
#undef SYM

    const int  M    = Bb * Ss;            // 4096
    const long SE   = (long)Ss * Ee;
    const long SL   = (long)Ss * Ll;
    const long HSL  = (long)Hh * SL;
    const long HDS  = (long)HDd * Ss;
    const long HHDS = (long)Hh * HDS;

    auto* G_BIG = gemm_pre<128, 128, 64, 32>;   // projections + scores
    auto* G_AV  = gemm_pre<128, 64, 32, 32>;    // attn @ V (N = 64)
    const int SM_BIG = 4 * (128 * 40 + 128 * 40) * 2;   // 81920 B
    const int SM_AV  = 4 * (128 * 40 + 64 * 40) * 2;    // 61440 B
    cudaFuncSetAttribute(G_BIG, cudaFuncAttributeMaxDynamicSharedMemorySize, SM_BIG);
    cudaFuncSetAttribute(G_AV,  cudaFuncAttributeMaxDynamicSharedMemorySize, SM_AV);

    dim3 gridL(Ee / 128, M / 128, 1);
    dim3 gridS(Ll / 128, Ss / 128, Bb * Hh);
    dim3 gridAV(1, Ss / 128, Bb * Hh);
    dim3 tb(32, 8);
    dim3 gridT768(Ee / 32, Ee / 32, 1);
    dim3 gridTK(Ss / 32, HDd / 32, Bb * Hh);
    const int pblk = (Ee * Ee + 255) / 256;
    const int sblk = (NELE / 4 + 255) / 256;

    // --- prep (ordered so launch idx 5 = first big GEMM for ncu -s 5) ------
    pack_w_split<<<pblk, 256>>>(w_kx1, wp0h, wp0l);                       // 0
    pack_w_split<<<pblk, 256>>>(w_qx1, wp1h, wp1l);                       // 1
    split_kernel<<<sblk, 256>>>(X, Xh, Xl, NELE / 4);                     // 2
    pack_w_split<<<pblk, 256>>>(w_kx2, wp2h, wp2l);                       // 3
    pack_w_split<<<pblk, 256>>>(w_qx2, wp3h, wp3l);                       // 4

    // ===================== Self-attention =====================
    G_BIG<<<gridL, 256, SM_BIG>>>(Xh, Xl, Ee, wp0h, wp0l, Ee,             // 5 (profiled)
                                  kx, kxh, kxl, Ee, Ee, 1.0f, nullptr, 0,
                                  1, 0, 0, 0, 0, 0, 0);
    G_BIG<<<gridL, 256, SM_BIG>>>(Xh, Xl, Ee, wp1h, wp1l, Ee,
                                  nullptr, qxh, qxl, Ee, Ee, 1.0f, nullptr, 0,
                                  1, 0, 0, 0, 0, 0, 0);
    transpose_kx_split<<<gridTK, tb>>>(kx, kxTh, kxTl);
    G_BIG<<<gridS, 256, SM_BIG>>>(qxh, qxl, Ee, kxh, kxl, Ee,
                                  sc, nullptr, nullptr, Ll, HDd, 0.125f, nullptr, 0,
                                  Hh, SE, HDd, SE, HDd, HSL, SL);
    softmax_split_kernel<<<Bb * Hh * Ss, 256>>>(sc, sch, scl, 0, nullptr);
    G_AV<<<gridAV, 256, SM_AV>>>(sch, scl, Ll, kxTh, kxTl, Ss,
                                 nullptr, atth, attl, Ee, Ll, 1.0f, nullptr, 0,
                                 Hh, HSL, SL, HHDS, HDS, SE, HDd);
    transpose768_split<<<gridT768, tb>>>(proj1_w, pT1h, pT1l);
    G_BIG<<<gridL, 256, SM_BIG>>>(atth, attl, Ee, pT1h, pT1l, Ee,
                                  tmp, nullptr, nullptr, Ee, Ee, 1.0f, proj1_b, 0,
                                  1, 0, 0, 0, 0, 0, 0);
    add_ln_kernel<<<M, 256>>>(tmp, X, ln1_w, ln1_b, Y, Yh, Yl);

    // ===================== Cross-attention =====================
    split_kernel<<<sblk, 256>>>(enc, ench, encl, NELE / 4);
    G_BIG<<<gridL, 256, SM_BIG>>>(ench, encl, Ee, wp2h, wp2l, Ee,
                                  kx, kxh, kxl, Ee, Ee, 1.0f, nullptr, 0,
                                  1, 0, 0, 0, 0, 0, 0);
    G_BIG<<<gridL, 256, SM_BIG>>>(Yh, Yl, Ee, wp3h, wp3l, Ee,
                                  nullptr, qxh, qxl, Ee, Ee, 1.0f, nullptr, 0,
                                  1, 0, 0, 0, 0, 0, 0);
    transpose_kx_split<<<gridTK, tb>>>(kx, kxTh, kxTl);
    G_BIG<<<gridS, 256, SM_BIG>>>(qxh, qxl, Ee, kxh, kxl, Ee,
                                  sc, nullptr, nullptr, Ll, HDd, 0.125f, nullptr, 0,
                                  Hh, SE, HDd, SE, HDd, HSL, SL);
    softmax_split_kernel<<<Bb * Hh * Ss, 256>>>(sc, sch, scl, 1, vlens);
    G_AV<<<gridAV, 256, SM_AV>>>(sch, scl, Ll, kxTh, kxTl, Ss,
                                 nullptr, atth, attl, Ee, Ll, 1.0f, nullptr, 0,
                                 Hh, HSL, SL, HHDS, HDS, SE, HDd);
    transpose768_split<<<gridT768, tb>>>(proj2_w, pT2h, pT2l);
    G_BIG<<<gridL, 256, SM_BIG>>>(atth, attl, Ee, pT2h, pT2l, Ee,
                                  tmp, nullptr, nullptr, Ee, Ee, 1.0f, proj2_b, 0,
                                  1, 0, 0, 0, 0, 0, 0);
    add_ln_kernel<<<M, 256>>>(tmp, Y, ln2_w, ln2_b, Z, Zh, Zl);

    // ===================== FFN =====================
    transpose768_split<<<gridT768, tb>>>(ffn_w1, fT1h, fT1l);
    transpose768_split<<<gridT768, tb>>>(ffn_w2, fT2h, fT2l);
    G_BIG<<<gridL, 256, SM_BIG>>>(Zh, Zl, Ee, fT1h, fT1l, Ee,
                                  nullptr, hidh, hidl, Ee, Ee, 1.0f, ffn_b1, 1,
                                  1, 0, 0, 0, 0, 0, 0);
    G_BIG<<<gridL, 256, SM_BIG>>>(hidh, hidl, Ee, fT2h, fT2l, Ee,
                                  tmp, nullptr, nullptr, Ee, Ee, 1.0f, ffn_b2, 0,
                                  1, 0, 0, 0, 0, 0, 0);
    add_ln_kernel<<<M, 256>>>(tmp, Z, ln3_w, ln3_b, (float*)d_out, nullptr, nullptr);
}